// round 9
// baseline (speedup 1.0000x reference)
#include <cuda_runtime.h>

// Fixed problem shapes
#define BB 8
#define LF 64
#define HWD 224
#define PLANE (HWD*HWD)        // 50176
#define FRAME (3*PLANE)        // 150528
#define NPAIR 63
#define MFR 16

// Diff-kernel tiling
#define RT 32                  // output rows per tile
#define NTILES 7               // 224/32
#define CHUNK 21               // pairs per chunk
#define NCHUNK 3               // 3*21 = 63
#define TPB 448                // blockDim = (224, 2)

#define VSTRIDE 233            // odd -> conflict-free strided access
#define PSTRIDE 225            // odd
#define SMEM_BYTES ((RT*VSTRIDE + RT*PSTRIDE) * 4)   // 58624

__device__ float g_part[BB * NPAIR * NTILES];
__device__ int   g_idx[BB * MFR];

// ---------------------------------------------------------------------------
// Kernel 1: streaming 7x7 box filter (separable, sliding window) + pair diff.
// Grid (tile=7, chunk=3, b=8) = 168 blocks. Block walks 22 frames (21 pairs).
// ---------------------------------------------------------------------------
__global__ void __launch_bounds__(TPB, 2)
diff_kernel(const float* __restrict__ x, const float* __restrict__ conv_w)
{
    const int tile  = blockIdx.x;
    const int chunk = blockIdx.y;
    const int b     = blockIdx.z;
    const int tx    = threadIdx.x;          // 0..223 (column)
    const int ty    = threadIdx.y;          // 0..1   (row half)
    const int t     = ty * 224 + tx;
    const int r0    = tile * RT;
    const int f0    = chunk * CHUNK;
    const float wscale = conv_w[0];         // all conv weights equal

    extern __shared__ float sm[];
    float* V = sm;                          // RT x VSTRIDE (vertical box sums)
    float* P = sm + RT * VSTRIDE;           // RT x PSTRIDE (prev frame y)
    __shared__ float red[TPB / 32];

    // zero the left (cols 0..3) / right (cols 228..232) pads of V, once
    for (int i = t; i < RT * 9; i += TPB) {
        int r = i / 9, k = i - r * 9;
        int col = (k < 4) ? k : (224 + k);
        V[r * VSTRIDE + col] = 0.f;
    }

    // phase-B thread mapping (hoisted out of the frame loop)
    const int row = t & 31;
    const int seg = t >> 5;                 // 0..13, 16 cols each
    const int c0  = seg * 16;
    const float* Vr = V + row * VSTRIDE;
    float*       Pr = P + row * PSTRIDE + c0;

    // phase-A bases
    const int grow0 = r0 + ty * 16 - 3;     // first input row for this thread
    const float* xb = x + (size_t)b * LF * FRAME + tx;

    // preload channel-sum column strip for the first frame (22 rows)
    float S[22];
    {
        const float* xf = xb + (size_t)f0 * FRAME;
        #pragma unroll
        for (int i = 0; i < 22; ++i) {
            int g = grow0 + i;
            float v = 0.f;
            if (g >= 0 && g < HWD) {
                const float* p = xf + (size_t)g * HWD;
                v = p[0] + p[PLANE] + p[2 * PLANE];
            }
            S[i] = v;
        }
    }

    for (int f = f0; f <= f0 + CHUNK; ++f) {
        // ---- phase A: vertical 7-tap sliding sum (registers -> SMEM V) ----
        {
            float s = S[0] + S[1] + S[2] + S[3] + S[4] + S[5] + S[6];
            float* vcol = V + (ty * 16) * VSTRIDE + 4 + tx;
            #pragma unroll
            for (int j = 0; j < 16; ++j) {
                vcol[j * VSTRIDE] = s;
                if (j < 15) s += S[j + 7] - S[j];
            }
        }
        __syncthreads();

        // ---- prefetch next frame's strip (LDGs overlap phase B below) ----
        if (f < f0 + CHUNK) {
            const float* xf = xb + (size_t)(f + 1) * FRAME;
            #pragma unroll
            for (int i = 0; i < 22; ++i) {
                int g = grow0 + i;
                float v = 0.f;
                if (g >= 0 && g < HWD) {
                    const float* p = xf + (size_t)g * HWD;
                    v = p[0] + p[PLANE] + p[2 * PLANE];
                }
                S[i] = v;
            }
        }

        // ---- phase B: horizontal 7-tap sliding sum + |diff| accumulate ----
        float acc = 0.f;
        {
            float hs = Vr[c0+1] + Vr[c0+2] + Vr[c0+3] + Vr[c0+4]
                     + Vr[c0+5] + Vr[c0+6] + Vr[c0+7];
            if (f > f0) {
                #pragma unroll
                for (int j = 0; j < 16; ++j) {
                    float y = wscale * hs;
                    acc += fabsf(Pr[j] - y + 1e-6f);
                    Pr[j] = y;
                    if (j < 15) hs += Vr[c0 + j + 8] - Vr[c0 + j + 1];
                }
            } else {
                #pragma unroll
                for (int j = 0; j < 16; ++j) {
                    Pr[j] = wscale * hs;
                    if (j < 15) hs += Vr[c0 + j + 8] - Vr[c0 + j + 1];
                }
            }
        }

        // ---- deterministic block reduction -> unique g_part slot ----
        if (f > f0) {
            #pragma unroll
            for (int o = 16; o; o >>= 1)
                acc += __shfl_down_sync(0xffffffffu, acc, o);
            if ((t & 31) == 0) red[t >> 5] = acc;
        }
        __syncthreads();
        if (f > f0 && t == 0) {
            float v = 0.f;
            #pragma unroll
            for (int i = 0; i < TPB / 32; ++i) v += red[i];
            g_part[((b * NPAIR) + (f - 1)) * NTILES + tile] = v;
        }
        __syncthreads();   // V/red safe to overwrite next frame
    }
}

// ---------------------------------------------------------------------------
// Kernel 2: reduce partials -> sqrt -> normalize -> cumsum -> argmin (tiny).
// ---------------------------------------------------------------------------
__global__ void select_kernel()
{
    int b = threadIdx.x;
    if (b >= BB) return;

    float cumarr[NPAIR];
    float sum = 0.f;
    for (int l = 0; l < NPAIR; ++l) {
        float ds = 0.f;
        const float* p = g_part + (b * NPAIR + l) * NTILES;
        #pragma unroll
        for (int tt = 0; tt < NTILES; ++tt) ds += p[tt];
        float v = sqrtf(ds);              // ds^((16/64)^0.5) = ds^0.5
        cumarr[l] = v;
        sum += v;
    }
    float c = 0.f;
    for (int l = 0; l < NPAIR; ++l) {
        c += cumarr[l] / sum;
        cumarr[l] = c;
    }
    const float interval = 1.0f / 15.0f;
    for (int m = 0; m < MFR; ++m) {
        float s = (float)m * interval;
        float best = 1e30f;
        int bi = 0;
        for (int l = 0; l < NPAIR; ++l) {
            float d = fabsf(cumarr[l] - s);
            if (d < best) { best = d; bi = l; }   // first-min == jnp.argmin
        }
        g_idx[b * MFR + m] = bi;
    }
}

// ---------------------------------------------------------------------------
// Kernel 3: gather selected frames (float4 streaming copy).
// ---------------------------------------------------------------------------
__global__ void gather_kernel(const float* __restrict__ x, float* __restrict__ out)
{
    const int F4 = FRAME / 4;              // 37632
    int i = blockIdx.x * blockDim.x + threadIdx.x;
    int total = BB * MFR * F4;
    if (i >= total) return;
    int frame = i / F4;
    int off   = i - frame * F4;
    int b = frame >> 4;
    int m = frame & 15;
    int l = g_idx[b * MFR + m];
    const float4* src = reinterpret_cast<const float4*>(x)
                        + ((size_t)(b * LF + l)) * F4 + off;
    reinterpret_cast<float4*>(out)[i] = *src;
}

// ---------------------------------------------------------------------------
extern "C" void kernel_launch(void* const* d_in, const int* in_sizes, int n_in,
                              void* d_out, int out_size)
{
    const float* x = (const float*)d_in[0];
    const float* w = (const float*)d_in[1];
    // conv bias (d_in[2]) cancels in the pairwise difference; unused.

    cudaFuncSetAttribute(diff_kernel, cudaFuncAttributeMaxDynamicSharedMemorySize,
                         SMEM_BYTES);

    dim3 g1(NTILES, NCHUNK, BB);
    dim3 b1(224, 2);
    diff_kernel<<<g1, b1, SMEM_BYTES>>>(x, w);

    select_kernel<<<1, 32>>>();

    int total4 = BB * MFR * (FRAME / 4);
    gather_kernel<<<(total4 + 255) / 256, 256>>>(x, (float*)d_out);
}

// round 11
// speedup vs baseline: 1.1188x; 1.1188x over previous
#include <cuda_runtime.h>

// Fixed problem shapes
#define BB 8
#define LF 64
#define HWD 224
#define PLANE (HWD*HWD)        // 50176
#define FRAME (3*PLANE)        // 150528
#define NPAIR 63
#define MFR 16

// Diff-kernel tiling
#define RT 32                  // output rows per tile
#define NTILES 7               // 224/32
#define CHUNK 7                // pairs per chunk
#define NCHUNK 9               // 9*7 = 63
#define TPB 448                // blockDim = (224, 2)

#define VSTRIDE 233            // odd -> conflict-free strided access
#define PSTRIDE 225            // odd
#define SMEM_BYTES ((RT*VSTRIDE + RT*PSTRIDE) * 4)   // 58624

__device__ float g_part[BB * NPAIR * NTILES];
__device__ int   g_idx[BB * MFR];

// ---------------------------------------------------------------------------
// Kernel 1: streaming 7x7 box filter (separable, sliding window) + pair diff.
// Grid (tile=7, chunk=9, b=8) = 504 blocks. Block walks 8 frames (7 pairs).
// ---------------------------------------------------------------------------
__global__ void __launch_bounds__(TPB, 2)
diff_kernel(const float* __restrict__ x, const float* __restrict__ conv_w)
{
    const int tile  = blockIdx.x;
    const int chunk = blockIdx.y;
    const int b     = blockIdx.z;
    const int tx    = threadIdx.x;          // 0..223 (column)
    const int ty    = threadIdx.y;          // 0..1   (row half)
    const int t     = ty * 224 + tx;
    const int r0    = tile * RT;
    const int f0    = chunk * CHUNK;
    const float wscale = conv_w[0];         // all conv weights equal

    extern __shared__ float sm[];
    float* V = sm;                          // RT x VSTRIDE (vertical box sums)
    float* P = sm + RT * VSTRIDE;           // RT x PSTRIDE (prev frame y)
    __shared__ float red[TPB / 32];

    // zero the left (cols 0..3) / right (cols 228..232) pads of V, once
    for (int i = t; i < RT * 9; i += TPB) {
        int r = i / 9, k = i - r * 9;
        int col = (k < 4) ? k : (224 + k);
        V[r * VSTRIDE + col] = 0.f;
    }

    // phase-B thread mapping (hoisted out of the frame loop)
    const int row = t & 31;
    const int seg = t >> 5;                 // 0..13, 16 cols each
    const int c0  = seg * 16;
    const float* Vr = V + row * VSTRIDE;
    float*       Pr = P + row * PSTRIDE + c0;

    // phase-A bases
    const int grow0 = r0 + ty * 16 - 3;     // first input row for this thread
    const float* xb = x + (size_t)b * LF * FRAME + tx;

    // preload channel-sum column strip for the first frame (22 rows)
    float S[22];
    {
        const float* xf = xb + (size_t)f0 * FRAME;
        #pragma unroll
        for (int i = 0; i < 22; ++i) {
            int g = grow0 + i;
            float v = 0.f;
            if (g >= 0 && g < HWD) {
                const float* p = xf + (size_t)g * HWD;
                v = p[0] + p[PLANE] + p[2 * PLANE];
            }
            S[i] = v;
        }
    }

    for (int f = f0; f <= f0 + CHUNK; ++f) {
        // ---- phase A: vertical 7-tap sliding sum (registers -> SMEM V) ----
        {
            float s = S[0] + S[1] + S[2] + S[3] + S[4] + S[5] + S[6];
            float* vcol = V + (ty * 16) * VSTRIDE + 4 + tx;
            #pragma unroll
            for (int j = 0; j < 16; ++j) {
                vcol[j * VSTRIDE] = s;
                if (j < 15) s += S[j + 7] - S[j];
            }
        }
        __syncthreads();

        // ---- prefetch next frame's strip (LDGs overlap phase B below) ----
        if (f < f0 + CHUNK) {
            const float* xf = xb + (size_t)(f + 1) * FRAME;
            #pragma unroll
            for (int i = 0; i < 22; ++i) {
                int g = grow0 + i;
                float v = 0.f;
                if (g >= 0 && g < HWD) {
                    const float* p = xf + (size_t)g * HWD;
                    v = p[0] + p[PLANE] + p[2 * PLANE];
                }
                S[i] = v;
            }
        }

        // ---- phase B: horizontal 7-tap sliding sum + |diff| accumulate ----
        float acc = 0.f;
        {
            float hs = Vr[c0+1] + Vr[c0+2] + Vr[c0+3] + Vr[c0+4]
                     + Vr[c0+5] + Vr[c0+6] + Vr[c0+7];
            if (f > f0) {
                #pragma unroll
                for (int j = 0; j < 16; ++j) {
                    float y = wscale * hs;
                    acc += fabsf(Pr[j] - y + 1e-6f);
                    Pr[j] = y;
                    if (j < 15) hs += Vr[c0 + j + 8] - Vr[c0 + j + 1];
                }
            } else {
                #pragma unroll
                for (int j = 0; j < 16; ++j) {
                    Pr[j] = wscale * hs;
                    if (j < 15) hs += Vr[c0 + j + 8] - Vr[c0 + j + 1];
                }
            }
        }

        // ---- deterministic block reduction -> unique g_part slot ----
        if (f > f0) {
            #pragma unroll
            for (int o = 16; o; o >>= 1)
                acc += __shfl_down_sync(0xffffffffu, acc, o);
            if ((t & 31) == 0) red[t >> 5] = acc;
        }
        __syncthreads();
        if (f > f0 && t == 0) {
            float v = 0.f;
            #pragma unroll
            for (int i = 0; i < TPB / 32; ++i) v += red[i];
            g_part[((b * NPAIR) + (f - 1)) * NTILES + tile] = v;
        }
        __syncthreads();   // V/red safe to overwrite next frame
    }
}

// ---------------------------------------------------------------------------
// Kernel 2: reduce partials -> sqrt -> normalize -> cumsum -> argmin (tiny).
// Kept strictly sequential per batch to match reference rounding order.
// ---------------------------------------------------------------------------
__global__ void select_kernel()
{
    int b = threadIdx.x;
    if (b >= BB) return;

    float cumarr[NPAIR];
    float sum = 0.f;
    for (int l = 0; l < NPAIR; ++l) {
        float ds = 0.f;
        const float* p = g_part + (b * NPAIR + l) * NTILES;
        #pragma unroll
        for (int tt = 0; tt < NTILES; ++tt) ds += p[tt];
        float v = sqrtf(ds);              // ds^((16/64)^0.5) = ds^0.5
        cumarr[l] = v;
        sum += v;
    }
    float c = 0.f;
    for (int l = 0; l < NPAIR; ++l) {
        c += cumarr[l] / sum;
        cumarr[l] = c;
    }
    const float interval = 1.0f / 15.0f;
    for (int m = 0; m < MFR; ++m) {
        float s = (float)m * interval;
        float best = 1e30f;
        int bi = 0;
        for (int l = 0; l < NPAIR; ++l) {
            float d = fabsf(cumarr[l] - s);
            if (d < best) { best = d; bi = l; }   // first-min == jnp.argmin
        }
        g_idx[b * MFR + m] = bi;
    }
}

// ---------------------------------------------------------------------------
// Kernel 3: gather selected frames (float4 streaming copy).
// ---------------------------------------------------------------------------
__global__ void gather_kernel(const float* __restrict__ x, float* __restrict__ out)
{
    const int F4 = FRAME / 4;              // 37632
    int i = blockIdx.x * blockDim.x + threadIdx.x;
    int total = BB * MFR * F4;
    if (i >= total) return;
    int frame = i / F4;
    int off   = i - frame * F4;
    int b = frame >> 4;
    int m = frame & 15;
    int l = g_idx[b * MFR + m];
    const float4* src = reinterpret_cast<const float4*>(x)
                        + ((size_t)(b * LF + l)) * F4 + off;
    reinterpret_cast<float4*>(out)[i] = *src;
}

// ---------------------------------------------------------------------------
extern "C" void kernel_launch(void* const* d_in, const int* in_sizes, int n_in,
                              void* d_out, int out_size)
{
    const float* x = (const float*)d_in[0];
    const float* w = (const float*)d_in[1];
    // conv bias (d_in[2]) cancels in the pairwise difference; unused.

    cudaFuncSetAttribute(diff_kernel, cudaFuncAttributeMaxDynamicSharedMemorySize,
                         SMEM_BYTES);

    dim3 g1(NTILES, NCHUNK, BB);
    dim3 b1(224, 2);
    diff_kernel<<<g1, b1, SMEM_BYTES>>>(x, w);

    select_kernel<<<1, 32>>>();

    int total4 = BB * MFR * (FRAME / 4);
    gather_kernel<<<(total4 + 255) / 256, 256>>>(x, (float*)d_out);
}